// round 15
// baseline (speedup 1.0000x reference)
#include <cuda_runtime.h>

#define N_B   16
#define C_INC 32
#define C_OC  64
#define HH    128
#define WWW   128
#define HW    16384
#define KK    800
#define NITER 8

// dynamic smem layout for corr kernel:
//   sa2: 32*128 ULL (pre-packed (x,x) duplicated pairs)       = 32768 B
//   sb2: 16*137 ULL (interleaved (c, c+16) channel pairs)     = 17536 B
#define SA2_ULL (32 * 128)
#define SB2_ULL (16 * 137)
#define CORR_SMEM ((SA2_ULL + SB2_ULL) * 8)

// ---------------- scratch (static device arrays; no allocation) ----------------
__device__ float g_R[N_B * C_INC * C_INC * 5 * 9];     // [n][c1][c2][dp 0..4][dq+4 0..8]
__device__ float g_Q[(size_t)N_B * KK * KK];           // [n][k1][k2]  (symmetric)
__device__ float g_P[N_B * C_OC * KK];                 // S accumulator -> RHS  [n][co][k]
__device__ float g_Rres[N_B * C_OC * KK];
__device__ float g_Pdir[N_B * C_OC * KK];
__device__ float g_W[N_B * C_OC * KK];
__device__ float g_rr[N_B * C_OC];
__device__ float g_pAp[N_B * C_OC];

// ---------------- f32x2 helpers ----------------
__device__ __forceinline__ unsigned long long pack2(float lo, float hi) {
    unsigned long long r;
    asm("mov.b64 %0, {%1, %2};" : "=l"(r) : "f"(lo), "f"(hi));
    return r;
}
__device__ __forceinline__ void fma2(unsigned long long& d, unsigned long long a, unsigned long long b) {
    asm("fma.rn.f32x2 %0, %1, %2, %0;" : "+l"(d) : "l"(a), "l"(b));
}
__device__ __forceinline__ float2 unpack2(unsigned long long v) {
    float2 f;
    asm("mov.b64 {%0, %1}, %2;" : "=f"(f.x), "=f"(f.y) : "l"(v));
    return f;
}

// ---------------- zero scratch accumulators ----------------
__global__ void zero_scratch_kernel() {
    int idx = blockIdx.x * 256 + threadIdx.x;           // grid covers 819200
    if (idx < N_B * C_INC * C_INC * 45) g_R[idx] = 0.f;
    if (idx < N_B * C_OC * KK)          g_P[idx] = 0.f;
    if (idx < N_B * C_OC * KK)          g_W[idx] = 0.f;
    if (idx < N_B * C_OC)               g_pAp[idx] = 0.f;
}

// ---------------- staging helpers (inside corr kernel) ----------------
// stage row 'src' (128 floats x 32 channels) as duplicated packed pairs into sa2
__device__ __forceinline__ void stage_a_packed(unsigned long long* sa2, const float* src,
                                               int tid) {
#pragma unroll
    for (int i = 0; i < 4; ++i) {
        int f = tid + i * 256;           // float4 index < 1024
        int c = f >> 5, v4 = f & 31;
        float4 val = *(const float4*)(src + c * HW + v4 * 4);
        unsigned long long* d = &sa2[c * 128 + v4 * 4];
        ((ulonglong2*)d)[0] = make_ulonglong2(pack2(val.x, val.x), pack2(val.y, val.y));
        ((ulonglong2*)d)[1] = make_ulonglong2(pack2(val.z, val.z), pack2(val.w, val.w));
    }
}
// stage row 'src' with 4-zero pad both sides, interleaved (c, c+16) pairs into sb2
__device__ __forceinline__ void stage_b_interleaved(float* sb2f, const float* src, int tid) {
#pragma unroll
    for (int i = 0; i < 17; ++i) {
        int f = tid + i * 256;
        if (f < 32 * 136) {
            int c = f / 136, t2 = f - c * 136;
            float v = 0.f;
            if (t2 >= 4 && t2 < 132) v = src[c * HW + (t2 - 4)];
            sb2f[((c & 15) * 137 + t2) * 2 + (c >> 4)] = v;
        }
    }
}

// ---------------- R-path body, templated on q range ----------------
template <int QBASE, int QN>
__device__ __forceinline__ void r_path(unsigned long long* sa2, unsigned long long* sb2,
                                       const float* xn, int n, int p, int u0,
                                       int tid, int tx, int ty) {
    float* sb2f = (float*)sb2;
    unsigned long long acc2[2][QN];
#pragma unroll
    for (int i = 0; i < 2; ++i)
#pragma unroll
        for (int q = 0; q < QN; ++q) acc2[i][q] = 0ULL;

    for (int u = u0; u < u0 + 8; ++u) {
        if (u + p >= HH) break;          // uniform
        __syncthreads();
        stage_a_packed(sa2, xn + u * WWW, tid);
        stage_b_interleaved(sb2f, xn + (u + p) * WWW, tid);
        __syncthreads();
        for (int v0 = 0; v0 < 128; v0 += 8) {
            unsigned long long ap0[8], ap1[8];
#pragma unroll
            for (int i = 0; i < 4; ++i) {
                *(ulonglong2*)&ap0[i * 2] = *(ulonglong2*)&sa2[ty * 128 + v0 + i * 2];
                *(ulonglong2*)&ap1[i * 2] = *(ulonglong2*)&sa2[(ty + 16) * 128 + v0 + i * 2];
            }
            unsigned long long bp[16];
#pragma unroll
            for (int t2 = 0; t2 < 16; ++t2) bp[t2] = sb2[tx * 137 + v0 + t2];
#pragma unroll
            for (int v = 0; v < 8; ++v) {
#pragma unroll
                for (int q = 0; q < QN; ++q) {
                    fma2(acc2[0][q], ap0[v], bp[v + QBASE + q]);
                    fma2(acc2[1][q], ap1[v], bp[v + QBASE + q]);
                }
            }
        }
    }
#pragma unroll
    for (int i = 0; i < 2; ++i) {
        int c1 = ty + i * 16;
#pragma unroll
        for (int q = 0; q < QN; ++q) {
            float2 f = unpack2(acc2[i][q]);
            atomicAdd(&g_R[(n * 1024 + c1 * 32 + tx) * 45 + p * 9 + QBASE + q], f.x);
            atomicAdd(&g_R[(n * 1024 + c1 * 32 + tx + 16) * 45 + p * 9 + QBASE + q], f.y);
        }
    }
}

// ---------------- unified correlation kernel ----------------
// blocks [0, 1280):  R path.  b = ((p*16 + n)*16 + chunk), u0 = chunk*8
//   (p==0 blocks compute only dq>=0; build_Q recovers dq<0 via transpose symmetry)
// blocks [1280, 3840): S path. b-1280 = ((di*16 + n)*32 + z), u0=(z>>1)*8, co0=(z&1)*32
__global__ __launch_bounds__(256, 2) void corr_kernel(const float* __restrict__ x,
                                                      const float* __restrict__ y) {
    extern __shared__ unsigned long long dsm[];
    unsigned long long* sa2 = dsm;                // SA2_ULL
    unsigned long long* sb2 = dsm + SA2_ULL;      // SB2_ULL
    float* sb2f = (float*)sb2;
    const int tid = threadIdx.x;
    const int tx = tid & 15, ty = tid >> 4;
    const int b = blockIdx.x;

    if (b < 1280) {
        const int chunk = b & 15;
        const int t = b >> 4;
        const int n = t & 15;
        const int p = t >> 4;           // 0..4
        const int u0 = chunk * 8;
        const float* xn = x + (size_t)n * C_INC * HW;
        if (p == 0) r_path<4, 5>(sa2, sb2, xn, n, p, u0, tid, tx, ty);
        else        r_path<0, 9>(sa2, sb2, xn, n, p, u0, tid, tx, ty);
    } else {
        // ---------- cross-correlation S ----------
        const int bb = b - 1280;
        const int z = bb & 31;
        const int t = bb >> 5;
        const int n = t & 15;
        const int di = t >> 4;          // 0..4
        const int u0 = (z >> 1) * 8;
        const int co0 = (z & 1) * 32;
        unsigned long long acc2[2][5];
#pragma unroll
        for (int i = 0; i < 2; ++i)
#pragma unroll
            for (int q = 0; q < 5; ++q) acc2[i][q] = 0ULL;

        const float* xn = x + (size_t)n * C_INC * HW;
        const float* yn = y + (size_t)n * C_OC * HW + (size_t)co0 * HW;
        const int ddi = di - 2;

        for (int u = u0; u < u0 + 8; ++u) {
            int ux = u + ddi;
            if (ux < 0) continue;        // uniform
            if (ux >= HH) break;         // uniform
            __syncthreads();
            stage_a_packed(sa2, yn + u * WWW, tid);
            stage_b_interleaved(sb2f, xn + ux * WWW, tid);
            __syncthreads();
            for (int v0 = 0; v0 < 128; v0 += 8) {
                unsigned long long ap0[8], ap1[8];
#pragma unroll
                for (int i = 0; i < 4; ++i) {
                    *(ulonglong2*)&ap0[i * 2] = *(ulonglong2*)&sa2[ty * 128 + v0 + i * 2];
                    *(ulonglong2*)&ap1[i * 2] = *(ulonglong2*)&sa2[(ty + 16) * 128 + v0 + i * 2];
                }
                unsigned long long bp[13];
#pragma unroll
                for (int t2 = 0; t2 < 13; ++t2) bp[t2] = sb2[tx * 137 + v0 + 2 + t2];
#pragma unroll
                for (int v = 0; v < 8; ++v) {
#pragma unroll
                    for (int q = 0; q < 5; ++q) {
                        fma2(acc2[0][q], ap0[v], bp[v + q]);   // x col = v + (q-2)
                        fma2(acc2[1][q], ap1[v], bp[v + q]);
                    }
                }
            }
        }
#pragma unroll
        for (int i = 0; i < 2; ++i) {
            int co = co0 + ty + i * 16;
#pragma unroll
            for (int q = 0; q < 5; ++q) {
                float2 f = unpack2(acc2[i][q]);
                atomicAdd(&g_P[(n * C_OC + co) * KK + tx * 25 + di * 5 + q], f.x);
                atomicAdd(&g_P[(n * C_OC + co) * KK + (tx + 16) * 25 + di * 5 + q], f.y);
            }
        }
    }
}

// ---------------- gather Q from R (+ a*I on diagonal), LUT-based ----------------
__global__ void build_Q_kernel(const float* __restrict__ alpha, const float* __restrict__ regp) {
    __shared__ int lut[KK];
    const int k1 = blockIdx.x, n = blockIdx.y, tid = threadIdx.x;
    for (int k = tid; k < KK; k += 256) {
        int c = k / 25, r = k - c * 25, bq = r / 5, fq = r - bq * 5;
        lut[k] = (c << 8) | (bq << 4) | fq;
    }
    __syncthreads();
    const int l1 = lut[k1];
    const int c1 = l1 >> 8, a1 = (l1 >> 4) & 15, e1 = l1 & 15;
    const float reg = regp ? regp[0] : 1.f;
    const float adiag = alpha[n] * ((float)HW * reg / (float)KK);
    const float* Rn = g_R + n * 1024 * 45;
    float* Qrow = g_Q + (size_t)n * (KK * KK) + (size_t)k1 * KK;
    for (int k2 = tid; k2 < KK; k2 += 256) {
        int l2 = lut[k2];
        int c2 = l2 >> 8, b2 = (l2 >> 4) & 15, f2 = l2 & 15;
        int dp = b2 - a1, dq = f2 - e1;
        float v;
        if (dp > 0 || (dp == 0 && dq >= 0))
            v = Rn[(c1 * 32 + c2) * 45 + dp * 9 + (dq + 4)];
        else
            v = Rn[(c2 * 32 + c1) * 45 + (-dp) * 9 + (4 - dq)];
        if (k2 == k1) v += adiag;
        Qrow[k2] = v;
    }
}

// ---------------- CG init: P += a*d ; Rres = Pdir = P ; X = 0 ; rr = |P|^2 ----------------
__global__ void cg_init_kernel(const float* __restrict__ dmat, const float* __restrict__ alpha,
                               const float* __restrict__ regp, float* __restrict__ X) {
    int co = blockIdx.x, n = blockIdx.y, tid = threadIdx.x;
    float reg = regp ? regp[0] : 1.f;
    float an = alpha[n] * ((float)HW * reg / (float)KK);
    int base = (n * C_OC + co) * KK;
    float local = 0.f;
    for (int k = tid; k < KK; k += 256) {
        float pv = g_P[base + k] + an * dmat[base + k];
        g_Rres[base + k] = pv;
        g_Pdir[base + k] = pv;
        X[base + k] = 0.f;
        local += pv * pv;
    }
    __shared__ float red[256];
    red[tid] = local; __syncthreads();
    for (int s = 128; s > 0; s >>= 1) { if (tid < s) red[tid] += red[tid + s]; __syncthreads(); }
    if (tid == 0) g_rr[n * C_OC + co] = red[0];
}

// ---------------- W += Pdir * Q (m-split in 4, atomic), with fused pAp partials ----------
__global__ __launch_bounds__(256) void matvec_kernel() {
    const int kb = blockIdx.x, n = blockIdx.z;
    const int s0 = (50 * blockIdx.y) / 4;          // in 16-row steps (uneven 12/13 split)
    const int s1 = (50 * (blockIdx.y + 1)) / 4;
    __shared__ unsigned long long As2[16][65];     // (a,a) packs: [m-in-tile][j]
    __shared__ unsigned long long Bs2[16][34];     // natural col pairs: [m-in-tile][colpair]
    const int tid = threadIdx.x;
    const int tx = tid & 15, ty = tid >> 4;
    unsigned long long acc2[4][2];
#pragma unroll
    for (int r = 0; r < 4; ++r) { acc2[r][0] = 0ULL; acc2[r][1] = 0ULL; }

    const float* Qn = g_Q + (size_t)n * (KK * KK);
    const float* Pn = g_Pdir + (n * C_OC) * KK;
    const int kb0 = kb * 64;
    const int aj = tid >> 2, at0 = (tid & 3) * 4;
    const int br = tid >> 4, bc0 = (tid & 15) * 4;

    for (int st = s0; st < s1; ++st) {
        const int m0 = st * 16;
        float4 av = *(const float4*)(Pn + aj * KK + m0 + at0);
        int col = kb0 + bc0;
        float4 bv;
        if (col + 3 < KK) bv = *(const float4*)(Qn + (size_t)(m0 + br) * KK + col);
        else              bv = make_float4(0.f, 0.f, 0.f, 0.f);
        __syncthreads();
        As2[at0 + 0][aj] = pack2(av.x, av.x);
        As2[at0 + 1][aj] = pack2(av.y, av.y);
        As2[at0 + 2][aj] = pack2(av.z, av.z);
        As2[at0 + 3][aj] = pack2(av.w, av.w);
        *(float4*)&Bs2[br][(tid & 15) * 2] = bv;
        __syncthreads();
#pragma unroll
        for (int kk = 0; kk < 16; ++kk) {
            unsigned long long bp0 = Bs2[kk][tx * 2];
            unsigned long long bp1 = Bs2[kk][tx * 2 + 1];
#pragma unroll
            for (int r = 0; r < 4; ++r) {
                unsigned long long ap = As2[kk][ty * 4 + r];
                fma2(acc2[r][0], ap, bp0);
                fma2(acc2[r][1], ap, bp1);
            }
        }
    }
    const int col0 = kb0 + tx * 4;
#pragma unroll
    for (int r = 0; r < 4; ++r) {
        float2 w01 = unpack2(acc2[r][0]);
        float2 w23 = unpack2(acc2[r][1]);
        int j = ty * 4 + r;
        float dot = 0.f;
        if (col0 < KK) {
            const float4 pv = *(const float4*)(g_Pdir + (n * C_OC + j) * KK + col0);
            dot = pv.x * w01.x + pv.y * w01.y + pv.z * w23.x + pv.w * w23.y;
            float* wd = g_W + (n * C_OC + j) * KK + col0;
            atomicAdd(wd + 0, w01.x);
            atomicAdd(wd + 1, w01.y);
            atomicAdd(wd + 2, w23.x);
            atomicAdd(wd + 3, w23.y);
        }
#pragma unroll
        for (int off = 8; off; off >>= 1) dot += __shfl_down_sync(0xffffffffu, dot, off, 16);
        if (tx == 0) atomicAdd(&g_pAp[n * C_OC + j], dot);
    }
}

// ---------------- fused CG update: alpha, x, r, rrnew, beta, p ; zero W & pAp -----------
__global__ void cg_update_kernel(float* __restrict__ X) {
    int j = blockIdx.x, n = blockIdx.y, tid = threadIdx.x;
    int id = n * C_OC + j, base = id * KK;
    float rr_old = g_rr[id];
    float alpha = rr_old / fmaxf(g_pAp[id], 1e-30f);
    float r[4], pd[4];
    float local = 0.f;
#pragma unroll
    for (int i = 0; i < 4; ++i) {
        int k = tid + i * 256;
        r[i] = 0.f; pd[i] = 0.f;
        if (k < KK) {
            pd[i] = g_Pdir[base + k];
            X[base + k] += alpha * pd[i];
            float rv = g_Rres[base + k] - alpha * g_W[base + k];
            g_Rres[base + k] = rv;
            g_W[base + k] = 0.f;          // ready for next matvec's atomics
            r[i] = rv;
            local += rv * rv;
        }
    }
    __shared__ float red[256];
    red[tid] = local; __syncthreads();
    for (int s = 128; s > 0; s >>= 1) { if (tid < s) red[tid] += red[tid + s]; __syncthreads(); }
    float rrnew = red[0];
    float beta = rrnew / fmaxf(rr_old, 1e-30f);
#pragma unroll
    for (int i = 0; i < 4; ++i) {
        int k = tid + i * 256;
        if (k < KK) g_Pdir[base + k] = r[i] + beta * pd[i];
    }
    if (tid == 0) { g_rr[id] = rrnew; g_pAp[id] = 0.f; }
}

// ---------------- launch ----------------
extern "C" void kernel_launch(void* const* d_in, const int* in_sizes, int n_in,
                              void* d_out, int out_size) {
    const float* x     = (const float*)d_in[0];
    const float* dmat  = (const float*)d_in[1];
    const float* y     = (const float*)d_in[2];
    const float* alpha = (const float*)d_in[3];
    const float* regp  = (n_in >= 5) ? (const float*)d_in[4] : nullptr;
    float* out = (float*)d_out;

    // function-metadata call (not stream-ordered, not an allocation); persists
    // across calls once set on the first (uncaptured) correctness invocation.
    cudaFuncSetAttribute(corr_kernel, cudaFuncAttributeMaxDynamicSharedMemorySize, CORR_SMEM);

    zero_scratch_kernel<<<3200, 256>>>();
    corr_kernel<<<3840, 256, CORR_SMEM>>>(x, y);
    build_Q_kernel<<<dim3(KK, 16), 256>>>(alpha, regp);
    cg_init_kernel<<<dim3(64, 16), 256>>>(dmat, alpha, regp, out);

    for (int it = 0; it < NITER; ++it) {
        matvec_kernel<<<dim3(13, 4, 16), 256>>>();
        cg_update_kernel<<<dim3(64, 16), 256>>>(out);
    }
    // out == X == Dsol in (n, c_out, c_in, ds, ds) layout already.
}

// round 16
// speedup vs baseline: 1.7866x; 1.7866x over previous
#include <cuda_runtime.h>

#define N_B   16
#define C_INC 32
#define C_OC  64
#define HH    128
#define WWW   128
#define HW    16384
#define KK    800
#define NITER 8

// ---------------- scratch (static device arrays; no allocation) ----------------
__device__ float g_R[N_B * C_INC * C_INC * 5 * 9];     // [n][c1][c2][dp 0..4][dq+4 0..8]
__device__ float g_Q[(size_t)N_B * KK * KK];           // [n][k1][k2]  (symmetric)
__device__ float g_P[N_B * C_OC * KK];                 // S accumulator -> RHS  [n][co][k]
__device__ float g_Rres[N_B * C_OC * KK];
__device__ float g_Pdir[N_B * C_OC * KK];
__device__ float g_W[N_B * C_OC * KK];
__device__ float g_rr[N_B * C_OC];
__device__ float g_pAp[N_B * C_OC];

// ---------------- f32x2 helpers ----------------
__device__ __forceinline__ unsigned long long pack2(float lo, float hi) {
    unsigned long long r;
    asm("mov.b64 %0, {%1, %2};" : "=l"(r) : "f"(lo), "f"(hi));
    return r;
}
__device__ __forceinline__ void fma2(unsigned long long& d, unsigned long long a, unsigned long long b) {
    asm("fma.rn.f32x2 %0, %1, %2, %0;" : "+l"(d) : "l"(a), "l"(b));
}
__device__ __forceinline__ float2 unpack2(unsigned long long v) {
    float2 f;
    asm("mov.b64 {%0, %1}, %2;" : "=f"(f.x), "=f"(f.y) : "l"(v));
    return f;
}

// ---------------- zero scratch accumulators ----------------
__global__ void zero_scratch_kernel() {
    int idx = blockIdx.x * 256 + threadIdx.x;           // grid covers 819200
    if (idx < N_B * C_INC * C_INC * 45) g_R[idx] = 0.f;
    if (idx < N_B * C_OC * KK)          g_P[idx] = 0.f;
    if (idx < N_B * C_OC * KK)          g_W[idx] = 0.f;
    if (idx < N_B * C_OC)               g_pAp[idx] = 0.f;
}

// ---------------- R-path body, templated on lag range (transient packs, float A regs) ----
template <int QBASE, int QN>
__device__ __forceinline__ void r_path(float (*sa)[128], unsigned long long* sb2,
                                       const float* xn, int n, int p, int u0,
                                       int tid, int tx, int ty) {
    float* sb2f = (float*)sb2;
    unsigned long long acc2[2][QN];
#pragma unroll
    for (int i = 0; i < 2; ++i)
#pragma unroll
        for (int q = 0; q < QN; ++q) acc2[i][q] = 0ULL;

    for (int u = u0; u < u0 + 8; ++u) {
        if (u + p >= HH) break;          // uniform
        __syncthreads();
#pragma unroll
        for (int i = 0; i < 4; ++i) {
            int f = tid + i * 256;       // float4 index < 1024
            int c = f >> 5, v4 = f & 31;
            *(float4*)&sa[c][v4 * 4] = *(const float4*)(xn + c * HW + u * WWW + v4 * 4);
        }
        {
            const int up = u + p;
#pragma unroll
            for (int i = 0; i < 17; ++i) {
                int f = tid + i * 256;
                if (f < C_INC * 136) {
                    int c = f / 136, t2 = f - c * 136;
                    float v = 0.f;
                    if (t2 >= 4 && t2 < 132) v = xn[c * HW + up * WWW + (t2 - 4)];
                    sb2f[((c & 15) * 137 + t2) * 2 + (c >> 4)] = v;
                }
            }
        }
        __syncthreads();
        for (int v0 = 0; v0 < 128; v0 += 8) {
            float a0[8], a1[8];
            *(float4*)&a0[0] = *(const float4*)&sa[ty][v0];
            *(float4*)&a0[4] = *(const float4*)&sa[ty][v0 + 4];
            *(float4*)&a1[0] = *(const float4*)&sa[ty + 16][v0];
            *(float4*)&a1[4] = *(const float4*)&sa[ty + 16][v0 + 4];
            unsigned long long bp[8 + QN];
#pragma unroll
            for (int t2 = 0; t2 < 8 + QN; ++t2) bp[t2] = sb2[tx * 137 + v0 + QBASE + t2];
#pragma unroll
            for (int v = 0; v < 8; ++v) {
                unsigned long long aa0 = pack2(a0[v], a0[v]);
                unsigned long long aa1 = pack2(a1[v], a1[v]);
#pragma unroll
                for (int q = 0; q < QN; ++q) {
                    fma2(acc2[0][q], aa0, bp[v + q]);
                    fma2(acc2[1][q], aa1, bp[v + q]);
                }
            }
        }
    }
#pragma unroll
    for (int i = 0; i < 2; ++i) {
        int c1 = ty + i * 16;
#pragma unroll
        for (int q = 0; q < QN; ++q) {
            float2 f = unpack2(acc2[i][q]);
            atomicAdd(&g_R[(n * 1024 + c1 * 32 + tx) * 45 + p * 9 + QBASE + q], f.x);
            atomicAdd(&g_R[(n * 1024 + c1 * 32 + tx + 16) * 45 + p * 9 + QBASE + q], f.y);
        }
    }
}

// ---------------- unified correlation kernel ----------------
// blocks [0, 1280):  R path.  b = ((p*16 + n)*16 + chunk), u0 = chunk*8
//   (p==0 blocks compute only dq>=0; build_Q recovers dq<0 via transpose symmetry)
// blocks [1280, 3840): S path. b-1280 = ((di*16 + n)*32 + z), u0=(z>>1)*8, co0=(z&1)*32
__global__ __launch_bounds__(256, 2) void corr_kernel(const float* __restrict__ x,
                                                      const float* __restrict__ y) {
    __shared__ float sa[C_INC][128];
    __shared__ unsigned long long sb2[16 * 137];   // interleaved (ch c, ch c+16) pairs, padded
    float* sb2f = (float*)sb2;
    const int tid = threadIdx.x;
    const int tx = tid & 15, ty = tid >> 4;
    const int b = blockIdx.x;

    if (b < 1280) {
        // ---------- autocorrelation R ----------
        const int chunk = b & 15;
        const int t = b >> 4;
        const int n = t & 15;
        const int p = t >> 4;           // 0..4
        const int u0 = chunk * 8;
        const float* xn = x + (size_t)n * C_INC * HW;
        if (p == 0) r_path<4, 5>(sa, sb2, xn, n, p, u0, tid, tx, ty);
        else        r_path<0, 9>(sa, sb2, xn, n, p, u0, tid, tx, ty);
    } else {
        // ---------- cross-correlation S ----------
        const int bb = b - 1280;
        const int z = bb & 31;
        const int t = bb >> 5;
        const int n = t & 15;
        const int di = t >> 4;          // 0..4
        const int u0 = (z >> 1) * 8;
        const int co0 = (z & 1) * 32;
        unsigned long long acc2[2][5];
#pragma unroll
        for (int i = 0; i < 2; ++i)
#pragma unroll
            for (int q = 0; q < 5; ++q) acc2[i][q] = 0ULL;

        const float* xn = x + (size_t)n * C_INC * HW;
        const float* yn = y + (size_t)n * C_OC * HW + (size_t)co0 * HW;
        const int ddi = di - 2;

        for (int u = u0; u < u0 + 8; ++u) {
            int ux = u + ddi;
            if (ux < 0) continue;        // uniform
            if (ux >= HH) break;         // uniform
            __syncthreads();
#pragma unroll
            for (int i = 0; i < 4; ++i) {
                int f = tid + i * 256;
                int c = f >> 5, v4 = f & 31;
                *(float4*)&sa[c][v4 * 4] = *(const float4*)(yn + c * HW + u * WWW + v4 * 4);
            }
#pragma unroll
            for (int i = 0; i < 17; ++i) {
                int f = tid + i * 256;
                if (f < 32 * 136) {
                    int c = f / 136, t2 = f - c * 136;
                    float v = 0.f;
                    if (t2 >= 4 && t2 < 132) v = xn[c * HW + ux * WWW + (t2 - 4)];
                    sb2f[((c & 15) * 137 + t2) * 2 + (c >> 4)] = v;
                }
            }
            __syncthreads();
            for (int v0 = 0; v0 < 128; v0 += 8) {
                float a0[8], a1[8];
                *(float4*)&a0[0] = *(const float4*)&sa[ty][v0];
                *(float4*)&a0[4] = *(const float4*)&sa[ty][v0 + 4];
                *(float4*)&a1[0] = *(const float4*)&sa[ty + 16][v0];
                *(float4*)&a1[4] = *(const float4*)&sa[ty + 16][v0 + 4];
                unsigned long long bp[13];
#pragma unroll
                for (int t2 = 0; t2 < 13; ++t2) bp[t2] = sb2[tx * 137 + v0 + 2 + t2];
#pragma unroll
                for (int v = 0; v < 8; ++v) {
                    unsigned long long aa0 = pack2(a0[v], a0[v]);
                    unsigned long long aa1 = pack2(a1[v], a1[v]);
#pragma unroll
                    for (int q = 0; q < 5; ++q) {
                        fma2(acc2[0][q], aa0, bp[v + q]);   // x col = v + (q-2)
                        fma2(acc2[1][q], aa1, bp[v + q]);
                    }
                }
            }
        }
#pragma unroll
        for (int i = 0; i < 2; ++i) {
            int co = co0 + ty + i * 16;
#pragma unroll
            for (int q = 0; q < 5; ++q) {
                float2 f = unpack2(acc2[i][q]);
                atomicAdd(&g_P[(n * C_OC + co) * KK + tx * 25 + di * 5 + q], f.x);
                atomicAdd(&g_P[(n * C_OC + co) * KK + (tx + 16) * 25 + di * 5 + q], f.y);
            }
        }
    }
}

// ---------------- gather Q from R (+ a*I on diagonal), LUT-based ----------------
__global__ void build_Q_kernel(const float* __restrict__ alpha, const float* __restrict__ regp) {
    __shared__ int lut[KK];
    const int k1 = blockIdx.x, n = blockIdx.y, tid = threadIdx.x;
    for (int k = tid; k < KK; k += 256) {
        int c = k / 25, r = k - c * 25, bq = r / 5, fq = r - bq * 5;
        lut[k] = (c << 8) | (bq << 4) | fq;
    }
    __syncthreads();
    const int l1 = lut[k1];
    const int c1 = l1 >> 8, a1 = (l1 >> 4) & 15, e1 = l1 & 15;
    const float reg = regp ? regp[0] : 1.f;
    const float adiag = alpha[n] * ((float)HW * reg / (float)KK);
    const float* Rn = g_R + n * 1024 * 45;
    float* Qrow = g_Q + (size_t)n * (KK * KK) + (size_t)k1 * KK;
    for (int k2 = tid; k2 < KK; k2 += 256) {
        int l2 = lut[k2];
        int c2 = l2 >> 8, b2 = (l2 >> 4) & 15, f2 = l2 & 15;
        int dp = b2 - a1, dq = f2 - e1;
        float v;
        if (dp > 0 || (dp == 0 && dq >= 0))
            v = Rn[(c1 * 32 + c2) * 45 + dp * 9 + (dq + 4)];
        else
            v = Rn[(c2 * 32 + c1) * 45 + (-dp) * 9 + (4 - dq)];
        if (k2 == k1) v += adiag;
        Qrow[k2] = v;
    }
}

// ---------------- CG init: P += a*d ; Rres = Pdir = P ; X = 0 ; rr = |P|^2 ----------------
__global__ void cg_init_kernel(const float* __restrict__ dmat, const float* __restrict__ alpha,
                               const float* __restrict__ regp, float* __restrict__ X) {
    int co = blockIdx.x, n = blockIdx.y, tid = threadIdx.x;
    float reg = regp ? regp[0] : 1.f;
    float an = alpha[n] * ((float)HW * reg / (float)KK);
    int base = (n * C_OC + co) * KK;
    float local = 0.f;
    for (int k = tid; k < KK; k += 256) {
        float pv = g_P[base + k] + an * dmat[base + k];
        g_Rres[base + k] = pv;
        g_Pdir[base + k] = pv;
        X[base + k] = 0.f;
        local += pv * pv;
    }
    __shared__ float red[256];
    red[tid] = local; __syncthreads();
    for (int s = 128; s > 0; s >>= 1) { if (tid < s) red[tid] += red[tid + s]; __syncthreads(); }
    if (tid == 0) g_rr[n * C_OC + co] = red[0];
}

// ---------------- W += Pdir * Q (m-split in 4, atomic), with fused pAp partials ----------
__global__ __launch_bounds__(256) void matvec_kernel() {
    const int kb = blockIdx.x, n = blockIdx.z;
    const int s0 = (50 * blockIdx.y) / 4;          // in 16-row steps (uneven 12/13 split)
    const int s1 = (50 * (blockIdx.y + 1)) / 4;
    __shared__ unsigned long long As2[16][65];     // (a,a) packs: [m-in-tile][j]
    __shared__ unsigned long long Bs2[16][34];     // natural col pairs: [m-in-tile][colpair]
    const int tid = threadIdx.x;
    const int tx = tid & 15, ty = tid >> 4;
    unsigned long long acc2[4][2];
#pragma unroll
    for (int r = 0; r < 4; ++r) { acc2[r][0] = 0ULL; acc2[r][1] = 0ULL; }

    const float* Qn = g_Q + (size_t)n * (KK * KK);
    const float* Pn = g_Pdir + (n * C_OC) * KK;
    const int kb0 = kb * 64;
    const int aj = tid >> 2, at0 = (tid & 3) * 4;
    const int br = tid >> 4, bc0 = (tid & 15) * 4;

    for (int st = s0; st < s1; ++st) {
        const int m0 = st * 16;
        float4 av = *(const float4*)(Pn + aj * KK + m0 + at0);
        int col = kb0 + bc0;
        float4 bv;
        if (col + 3 < KK) bv = *(const float4*)(Qn + (size_t)(m0 + br) * KK + col);
        else              bv = make_float4(0.f, 0.f, 0.f, 0.f);
        __syncthreads();
        As2[at0 + 0][aj] = pack2(av.x, av.x);
        As2[at0 + 1][aj] = pack2(av.y, av.y);
        As2[at0 + 2][aj] = pack2(av.z, av.z);
        As2[at0 + 3][aj] = pack2(av.w, av.w);
        *(float4*)&Bs2[br][(tid & 15) * 2] = bv;
        __syncthreads();
#pragma unroll
        for (int kk = 0; kk < 16; ++kk) {
            unsigned long long bp0 = Bs2[kk][tx * 2];
            unsigned long long bp1 = Bs2[kk][tx * 2 + 1];
#pragma unroll
            for (int r = 0; r < 4; ++r) {
                unsigned long long ap = As2[kk][ty * 4 + r];
                fma2(acc2[r][0], ap, bp0);
                fma2(acc2[r][1], ap, bp1);
            }
        }
    }
    const int col0 = kb0 + tx * 4;
#pragma unroll
    for (int r = 0; r < 4; ++r) {
        float2 w01 = unpack2(acc2[r][0]);
        float2 w23 = unpack2(acc2[r][1]);
        int j = ty * 4 + r;
        float dot = 0.f;
        if (col0 < KK) {
            const float4 pv = *(const float4*)(g_Pdir + (n * C_OC + j) * KK + col0);
            dot = pv.x * w01.x + pv.y * w01.y + pv.z * w23.x + pv.w * w23.y;
            float* wd = g_W + (n * C_OC + j) * KK + col0;
            atomicAdd(wd + 0, w01.x);
            atomicAdd(wd + 1, w01.y);
            atomicAdd(wd + 2, w23.x);
            atomicAdd(wd + 3, w23.y);
        }
#pragma unroll
        for (int off = 8; off; off >>= 1) dot += __shfl_down_sync(0xffffffffu, dot, off, 16);
        if (tx == 0) atomicAdd(&g_pAp[n * C_OC + j], dot);
    }
}

// ---------------- fused CG update: alpha, x, r, rrnew, beta, p ; zero W & pAp -----------
__global__ void cg_update_kernel(float* __restrict__ X) {
    int j = blockIdx.x, n = blockIdx.y, tid = threadIdx.x;
    int id = n * C_OC + j, base = id * KK;
    float rr_old = g_rr[id];
    float alpha = rr_old / fmaxf(g_pAp[id], 1e-30f);
    float r[4], pd[4];
    float local = 0.f;
#pragma unroll
    for (int i = 0; i < 4; ++i) {
        int k = tid + i * 256;
        r[i] = 0.f; pd[i] = 0.f;
        if (k < KK) {
            pd[i] = g_Pdir[base + k];
            X[base + k] += alpha * pd[i];
            float rv = g_Rres[base + k] - alpha * g_W[base + k];
            g_Rres[base + k] = rv;
            g_W[base + k] = 0.f;          // ready for next matvec's atomics
            r[i] = rv;
            local += rv * rv;
        }
    }
    __shared__ float red[256];
    red[tid] = local; __syncthreads();
    for (int s = 128; s > 0; s >>= 1) { if (tid < s) red[tid] += red[tid + s]; __syncthreads(); }
    float rrnew = red[0];
    float beta = rrnew / fmaxf(rr_old, 1e-30f);
#pragma unroll
    for (int i = 0; i < 4; ++i) {
        int k = tid + i * 256;
        if (k < KK) g_Pdir[base + k] = r[i] + beta * pd[i];
    }
    if (tid == 0) { g_rr[id] = rrnew; g_pAp[id] = 0.f; }
}

// ---------------- launch ----------------
extern "C" void kernel_launch(void* const* d_in, const int* in_sizes, int n_in,
                              void* d_out, int out_size) {
    const float* x     = (const float*)d_in[0];
    const float* dmat  = (const float*)d_in[1];
    const float* y     = (const float*)d_in[2];
    const float* alpha = (const float*)d_in[3];
    const float* regp  = (n_in >= 5) ? (const float*)d_in[4] : nullptr;
    float* out = (float*)d_out;

    zero_scratch_kernel<<<3200, 256>>>();
    corr_kernel<<<3840, 256>>>(x, y);
    build_Q_kernel<<<dim3(KK, 16), 256>>>(alpha, regp);
    cg_init_kernel<<<dim3(64, 16), 256>>>(dmat, alpha, regp, out);

    for (int it = 0; it < NITER; ++it) {
        matvec_kernel<<<dim3(13, 4, 16), 256>>>();
        cg_update_kernel<<<dim3(64, 16), 256>>>(out);
    }
    // out == X == Dsol in (n, c_out, c_in, ds, ds) layout already.
}